// round 14
// baseline (speedup 1.0000x reference)
#include <cuda_runtime.h>
#include <cuda_fp16.h>
#include <cuda_bf16.h>
#include <math.h>
#include <stdint.h>

#define BATCH   8
#define NN      64
#define KTOT    65536
#define SPLITS  32
#define KCH     (KTOT / SPLITS)   // 2048
#define TILE_K  128               // floats per tile row (512B bursts)
#define NTILES  (KCH / TILE_K)    // 16
#define HSTRIDE 136               // fp16 smem row stride (272B)
#define ITERS   10
#define NTHREADS 384              // 8 consumer + 4 producer warps

// Gram scratch [B][N][N]; zero at module load, re-zeroed by the crf CTAs.
__device__ float g_gram[BATCH * NN * NN];
// Per-batch gram-CTA arrival counters; reset by the crf CTAs each call.
__device__ unsigned int g_cnt[BATCH];

__device__ __forceinline__ uint32_t smem_u32(const void* p) {
    return (uint32_t)__cvta_generic_to_shared(p);
}

#define BAR_SYNC(id)   asm volatile("bar.sync %0, 384;"   :: "r"(id) : "memory")
#define BAR_ARRIVE(id) asm volatile("bar.arrive %0, 384;" :: "r"(id) : "memory")
// consumer-only barrier (producers have exited by the time this runs)
#define BAR_SYNC_CONS(id) asm volatile("bar.sync %0, 256;" :: "r"(id) : "memory")

// ---------------------------------------------------------------------------
// One kernel, two CTA roles:
//  blockIdx.x <  SPLITS : warp-specialized gram CTA (R12 code, unchanged)
//  blockIdx.x == SPLITS : crf CTA for batch blockIdx.y — spins until its 32
//                         gram CTAs arrive, then runs the CRF tail + output.
// grid = (SPLITS+1, BATCH) = 264 CTAs, 384 thr, occ 2 -> all co-resident.
// ---------------------------------------------------------------------------
__global__ void __launch_bounds__(NTHREADS, 2) gram_crf_kernel(const float* __restrict__ feats,
                                                               const float* __restrict__ logits,
                                                               const float* __restrict__ W,
                                                               float* __restrict__ out) {
    __shared__ __align__(16) __half hbuf[2][64 * HSTRIDE];   // 2 x 17 KB (gram)
    __shared__ float s_nrm[64];                              // (crf)
    __shared__ float s_lg[64];
    __shared__ float s_e[2][64];
    __shared__ float s_red[64];

    const int tid  = threadIdx.x;
    const int wid  = tid >> 5;
    const int lane = tid & 31;
    const int b    = blockIdx.y;

    // ======================= CRF CTA =======================
    if (blockIdx.x == SPLITS) {
        // spin until all gram CTAs of batch b have accumulated
        if (tid == 0) {
            while (atomicAdd(&g_cnt[b], 0u) < (unsigned)SPLITS) {
                __nanosleep(200);
            }
            g_cnt[b] = 0;   // reset for next graph replay
        }
        __syncthreads();
        __threadfence();    // order subsequent g_gram reads after the observation

        float* gb = g_gram + (size_t)b * NN * NN;
        const int i  = tid >> 2;      // valid for tid < 256
        const int q  = tid & 3;
        const int j0 = q * 16;
        const bool act = (tid < 256);

        if (tid < 64) {
            s_nrm[tid]  = sqrtf(gb[tid * NN + tid]);
            s_lg[tid]   = logits[b * NN + tid];
            s_e[0][tid] = 0.0f;
        }
        __syncthreads();

        float pp[16];
        float li = 0.0f;
        if (act) {
            const float ni = s_nrm[i];
#pragma unroll
            for (int jj = 0; jj < 16; ++jj) {
                const int j = j0 + jj;
                const float dot  = gb[i * NN + j];
                const float sim  = dot / (ni * s_nrm[j] + 1e-6f);
                const float wsym = 0.5f * (W[i * NN + j] + W[j * NN + i]);
                pp[jj] = sim * wsym;
            }
            // re-zero consumed gram slice for the next replay
#pragma unroll
            for (int jj = 0; jj < 16; jj += 4)
                *reinterpret_cast<float4*>(&gb[i * NN + j0 + jj]) = make_float4(0.f, 0.f, 0.f, 0.f);
            li = s_lg[i];
        }

        int cur = 0;
        for (int it = 0; it < ITERS; ++it) {
            if (act) {
                float acc = 0.0f;
                const float* e = s_e[cur];
#pragma unroll
                for (int jj = 0; jj < 16; ++jj) {
                    const float x = li + e[j0 + jj];
                    float t, r;
                    asm("ex2.approx.f32 %0, %1;" : "=f"(t) : "f"(x * -1.4426950408889634f));
                    asm("rcp.approx.f32 %0, %1;" : "=f"(r) : "f"(1.0f + t));
                    acc = fmaf((1.0f - t) * r, pp[jj], acc);
                }
                acc += __shfl_xor_sync(0xFFFFFFFF, acc, 1);
                acc += __shfl_xor_sync(0xFFFFFFFF, acc, 2);
                if (q == 0) s_e[cur ^ 1][i] = acc;
            }
            __syncthreads();
            cur ^= 1;
        }

        if (tid < 64) s_red[tid] = s_e[cur][tid];
        __syncthreads();
        if (tid < 32) {
            float v = s_red[tid] + s_red[tid + 32];
            v += __shfl_xor_sync(0xFFFFFFFF, v, 16);
            v += __shfl_xor_sync(0xFFFFFFFF, v, 8);
            v += __shfl_xor_sync(0xFFFFFFFF, v, 4);
            v += __shfl_xor_sync(0xFFFFFFFF, v, 2);
            v += __shfl_xor_sync(0xFFFFFFFF, v, 1);
            if (tid == 0) s_red[0] = v;
        }
        __syncthreads();
        if (tid < 64) {
            const float meanE = s_red[0] * (1.0f / 64.0f);
            out[b * NN + tid] = s_lg[tid] + meanE;
        }
        return;
    }

    // ======================= GRAM CTA (R12, unchanged) =======================
    const int s = blockIdx.x;
    const float* base = feats + (size_t)b * NN * KTOT + (size_t)s * KCH;

    if (wid >= 8) {
        // producer warps (4): rows [16*pw, 16*pw+16)
        const int pw = wid - 8;
        const int rbase = pw * 16;
        for (int t = 0; t < NTILES; ++t) {
            const int buf = t & 1;
            if (t >= 2) BAR_SYNC(3 + buf);
            const float* g = base + t * TILE_K;
#pragma unroll
            for (int h = 0; h < 2; ++h) {
                float4 v[8];
#pragma unroll
                for (int i = 0; i < 8; ++i) {
                    const int row = rbase + h * 8 + i;
                    v[i] = *reinterpret_cast<const float4*>(g + (size_t)row * KTOT + lane * 4);
                }
#pragma unroll
                for (int i = 0; i < 8; ++i) {
                    const int row = rbase + h * 8 + i;
                    __half2 h0 = __float22half2_rn(make_float2(v[i].x, v[i].y));
                    __half2 h1 = __float22half2_rn(make_float2(v[i].z, v[i].w));
                    uint2 w = make_uint2(*(uint32_t*)&h0, *(uint32_t*)&h1);
                    *reinterpret_cast<uint2*>(&hbuf[buf][row * HSTRIDE + lane * 4]) = w;
                }
            }
            BAR_ARRIVE(1 + buf);
        }
        return;                                     // producers exit
    }

    const int tg = lane & 3;
    const int wm = wid >> 1;
    const int wn = wid & 1;

    const int a_row  = wm * 16 + (lane & 7) + ((lane >> 3) & 1) * 8;
    const int a_koff = (lane >> 4) * 8;
    const int b_col  = wn * 32 + (lane & 7) + ((lane >> 4) & 1) * 8;
    const int b_koff = ((lane >> 3) & 1) * 8;

    float c[4][4];
#pragma unroll
    for (int i = 0; i < 4; ++i)
#pragma unroll
        for (int j = 0; j < 4; ++j) c[i][j] = 0.0f;

    for (int t = 0; t < NTILES; ++t) {
        const int buf = t & 1;
        BAR_SYNC(1 + buf);

        const __half* S = &hbuf[buf][0];
#pragma unroll
        for (int kk = 0; kk < 8; ++kk) {
            const int k0 = kk * 16;
            uint32_t a0, a1, a2, a3, b01[2], b23[2], b45[2], b67[2];
            {
                uint32_t addr = smem_u32(S + a_row * HSTRIDE + k0 + a_koff);
                asm volatile("ldmatrix.sync.aligned.m8n8.x4.shared.b16 {%0,%1,%2,%3}, [%4];"
                             : "=r"(a0), "=r"(a1), "=r"(a2), "=r"(a3) : "r"(addr));
            }
            {
                uint32_t addr = smem_u32(S + b_col * HSTRIDE + k0 + b_koff);
                asm volatile("ldmatrix.sync.aligned.m8n8.x4.shared.b16 {%0,%1,%2,%3}, [%4];"
                             : "=r"(b01[0]), "=r"(b01[1]), "=r"(b23[0]), "=r"(b23[1]) : "r"(addr));
            }
            {
                uint32_t addr = smem_u32(S + (b_col + 16) * HSTRIDE + k0 + b_koff);
                asm volatile("ldmatrix.sync.aligned.m8n8.x4.shared.b16 {%0,%1,%2,%3}, [%4];"
                             : "=r"(b45[0]), "=r"(b45[1]), "=r"(b67[0]), "=r"(b67[1]) : "r"(addr));
            }
#define MMA16(accv, bb)                                                         \
    asm volatile("mma.sync.aligned.m16n8k16.row.col.f32.f16.f16.f32 "          \
                 "{%0,%1,%2,%3}, {%4,%5,%6,%7}, {%8,%9}, {%0,%1,%2,%3};"       \
                 : "+f"(accv[0]), "+f"(accv[1]), "+f"(accv[2]), "+f"(accv[3])  \
                 : "r"(a0), "r"(a1), "r"(a2), "r"(a3), "r"(bb[0]), "r"(bb[1]))
            MMA16(c[0], b01);
            MMA16(c[1], b23);
            MMA16(c[2], b45);
            MMA16(c[3], b67);
#undef MMA16
        }
        BAR_ARRIVE(3 + buf);
    }

    // epilogue: atomic-accumulate partial C, then bump the batch counter
    float* gb = g_gram + (size_t)b * NN * NN;
    const int re = wm * 16 + (lane >> 2);
#pragma unroll
    for (int nt = 0; nt < 4; ++nt) {
        const int col = wn * 32 + nt * 8 + tg * 2;
        atomicAdd(&gb[(re)     * NN + col    ], c[nt][0]);
        atomicAdd(&gb[(re)     * NN + col + 1], c[nt][1]);
        atomicAdd(&gb[(re + 8) * NN + col    ], c[nt][2]);
        atomicAdd(&gb[(re + 8) * NN + col + 1], c[nt][3]);
    }
    __threadfence();                  // partials visible before the ticket
    BAR_SYNC_CONS(5);                 // consumer warps only (256) — producers exited
    if (tid == 0) atomicAdd(&g_cnt[b], 1u);
}

extern "C" void kernel_launch(void* const* d_in, const int* in_sizes, int n_in,
                              void* d_out, int out_size) {
    const float* a_inter = (const float*)d_in[0];  // [8,64,64,32,32]
    const float* logits  = (const float*)d_in[1];  // [8,64]
    const float* W       = (const float*)d_in[2];  // [1,64,64]
    float* out           = (float*)d_out;          // [8,64]

    dim3 grid(SPLITS + 1, BATCH);
    gram_crf_kernel<<<grid, NTHREADS>>>(a_inter, logits, W, out);
}

// round 15
// speedup vs baseline: 1.0710x; 1.0710x over previous
#include <cuda_runtime.h>
#include <cuda_fp16.h>
#include <cuda_bf16.h>
#include <math.h>
#include <stdint.h>

#define BATCH   8
#define NN      64
#define KTOT    65536
#define SPLITS  32
#define KCH     (KTOT / SPLITS)   // 2048
#define TILE_K  128               // floats per tile row (512B cp.async bursts)
#define NTILES  (KCH / TILE_K)    // 16
#define FSTRIDE 132               // fp32 staging row stride (floats)
#define HSTRIDE 136               // fp16 smem row stride (halves)
#define ITERS   10
#define NTHREADS 384              // 8 consumer + 4 producer warps

#define FSTAGE_ELEMS (64 * FSTRIDE)            // per stage buffer
#define HBUF_ELEMS   (64 * HSTRIDE)
#define DSMEM_BYTES  (2 * FSTAGE_ELEMS * 4 + 2 * HBUF_ELEMS * 2)   // 102400

// Gram scratch [B][N][N]; zero at module load, re-zeroed by crf_kernel.
__device__ float g_gram[BATCH * NN * NN];

__device__ __forceinline__ uint32_t smem_u32(const void* p) {
    return (uint32_t)__cvta_generic_to_shared(p);
}

#define BAR_SYNC(id)   asm volatile("bar.sync %0, 384;"   :: "r"(id) : "memory")
#define BAR_ARRIVE(id) asm volatile("bar.arrive %0, 384;" :: "r"(id) : "memory")

// ---------------------------------------------------------------------------
// Kernel 1: warp-specialized split-K Gram, cp.async producer path.
// grid = (SPLITS, BATCH) = 256 CTAs, block = 384, occ 2 -> single wave.
// Producer warps: cp.async fp32 tiles (512B/row bursts, prefetch dist 2),
//   then LDS->cvt->STS convert into fp16 hbuf. Consumers: R12 mma pipeline.
// ---------------------------------------------------------------------------
__global__ void __launch_bounds__(NTHREADS, 2) gram_mma_kernel(const float* __restrict__ feats) {
    extern __shared__ __align__(16) char dsm[];
    float*  fstage = reinterpret_cast<float*>(dsm);                          // [2][64*FSTRIDE]
    __half* hbuf   = reinterpret_cast<__half*>(dsm + 2 * FSTAGE_ELEMS * 4);  // [2][64*HSTRIDE]

    const int tid  = threadIdx.x;
    const int wid  = tid >> 5;
    const int lane = tid & 31;

    const int b = blockIdx.y;
    const int s = blockIdx.x;
    const float* base = feats + (size_t)b * NN * KTOT + (size_t)s * KCH;

    if (wid >= 8) {
        // -------- producer warps (4): rows [16*pw, 16*pw+16) --------
        const int pw = wid - 8;
        const int rbase = pw * 16;

#define CP_TILE(stg, t)                                                          \
    do {                                                                         \
        const float* g = base + (t) * TILE_K;                                    \
        _Pragma("unroll")                                                        \
        for (int i = 0; i < 16; ++i) {                                           \
            const int row = rbase + i;                                           \
            uint32_t dst = smem_u32(&fstage[(stg) * FSTAGE_ELEMS + row * FSTRIDE + lane * 4]); \
            const float* src = g + (size_t)row * KTOT + lane * 4;                \
            asm volatile("cp.async.cg.shared.global [%0], [%1], 16;"             \
                         :: "r"(dst), "l"(src));                                 \
        }                                                                        \
        asm volatile("cp.async.commit_group;" ::: "memory");                     \
    } while (0)

        // prologue: tiles 0 and 1 in flight
        CP_TILE(0, 0);
        CP_TILE(1, 1);

        for (int t = 0; t < NTILES; ++t) {
            const int buf = t & 1;
            // stage[buf] holds tile t; ensure its group completed
            if (t + 1 < NTILES) {
                asm volatile("cp.async.wait_group 1;" ::: "memory");
            } else {
                asm volatile("cp.async.wait_group 0;" ::: "memory");
            }
            if (t >= 2) BAR_SYNC(3 + buf);      // consumers done with hbuf[buf]

            // convert fstage[buf] tile -> hbuf[buf] (LDS.128 + cvt + STS.64)
#pragma unroll
            for (int i = 0; i < 16; ++i) {
                const int row = rbase + i;
                float4 v = *reinterpret_cast<const float4*>(
                    &fstage[buf * FSTAGE_ELEMS + row * FSTRIDE + lane * 4]);
                __half2 h0 = __float22half2_rn(make_float2(v.x, v.y));
                __half2 h1 = __float22half2_rn(make_float2(v.z, v.w));
                uint2 w = make_uint2(*(uint32_t*)&h0, *(uint32_t*)&h1);
                *reinterpret_cast<uint2*>(
                    &hbuf[buf * HBUF_ELEMS + row * HSTRIDE + lane * 4]) = w;
            }
            BAR_ARRIVE(1 + buf);                // hbuf[buf] full

            // refill the stage we just drained with tile t+2
            if (t + 2 < NTILES) CP_TILE(buf, t + 2);
        }
#undef CP_TILE
        return;                                 // producers exit
    }

    // -------- consumer warps (8): 4(M) x 2(N) mma layout --------
    const int tg = lane & 3;
    const int wm = wid >> 1;
    const int wn = wid & 1;

    const int a_row  = wm * 16 + (lane & 7) + ((lane >> 3) & 1) * 8;
    const int a_koff = (lane >> 4) * 8;
    const int b_col  = wn * 32 + (lane & 7) + ((lane >> 4) & 1) * 8;
    const int b_koff = ((lane >> 3) & 1) * 8;

    float c[4][4];
#pragma unroll
    for (int i = 0; i < 4; ++i)
#pragma unroll
        for (int j = 0; j < 4; ++j) c[i][j] = 0.0f;

    for (int t = 0; t < NTILES; ++t) {
        const int buf = t & 1;
        BAR_SYNC(1 + buf);                      // wait hbuf[buf] full

        const __half* S = &hbuf[buf * HBUF_ELEMS];
#pragma unroll
        for (int kk = 0; kk < 8; ++kk) {
            const int k0 = kk * 16;
            uint32_t a0, a1, a2, a3, b01[2], b23[2], b45[2], b67[2];
            {
                uint32_t addr = smem_u32(S + a_row * HSTRIDE + k0 + a_koff);
                asm volatile("ldmatrix.sync.aligned.m8n8.x4.shared.b16 {%0,%1,%2,%3}, [%4];"
                             : "=r"(a0), "=r"(a1), "=r"(a2), "=r"(a3) : "r"(addr));
            }
            {
                uint32_t addr = smem_u32(S + b_col * HSTRIDE + k0 + b_koff);
                asm volatile("ldmatrix.sync.aligned.m8n8.x4.shared.b16 {%0,%1,%2,%3}, [%4];"
                             : "=r"(b01[0]), "=r"(b01[1]), "=r"(b23[0]), "=r"(b23[1]) : "r"(addr));
            }
            {
                uint32_t addr = smem_u32(S + (b_col + 16) * HSTRIDE + k0 + b_koff);
                asm volatile("ldmatrix.sync.aligned.m8n8.x4.shared.b16 {%0,%1,%2,%3}, [%4];"
                             : "=r"(b45[0]), "=r"(b45[1]), "=r"(b67[0]), "=r"(b67[1]) : "r"(addr));
            }
#define MMA16(accv, bb)                                                         \
    asm volatile("mma.sync.aligned.m16n8k16.row.col.f32.f16.f16.f32 "          \
                 "{%0,%1,%2,%3}, {%4,%5,%6,%7}, {%8,%9}, {%0,%1,%2,%3};"       \
                 : "+f"(accv[0]), "+f"(accv[1]), "+f"(accv[2]), "+f"(accv[3])  \
                 : "r"(a0), "r"(a1), "r"(a2), "r"(a3), "r"(bb[0]), "r"(bb[1]))
            MMA16(c[0], b01);
            MMA16(c[1], b23);
            MMA16(c[2], b45);
            MMA16(c[3], b67);
#undef MMA16
        }
        BAR_ARRIVE(3 + buf);                    // hbuf[buf] empty
    }

    // epilogue: atomic-accumulate partial C into g_gram[b]
    float* gb = g_gram + (size_t)b * NN * NN;
    const int re = wm * 16 + (lane >> 2);
#pragma unroll
    for (int nt = 0; nt < 4; ++nt) {
        const int col = wn * 32 + nt * 8 + tg * 2;
        atomicAdd(&gb[(re)     * NN + col    ], c[nt][0]);
        atomicAdd(&gb[(re)     * NN + col + 1], c[nt][1]);
        atomicAdd(&gb[(re + 8) * NN + col    ], c[nt][2]);
        atomicAdd(&gb[(re + 8) * NN + col + 1], c[nt][3]);
    }
}

// ---------------------------------------------------------------------------
// Kernel 2: CRF iterations + output (R7/R9 scheme). grid = BATCH, block = 256.
// Also re-zeroes g_gram for the next graph replay.
// ---------------------------------------------------------------------------
__global__ void __launch_bounds__(256) crf_kernel(const float* __restrict__ logits,
                                                  const float* __restrict__ W,
                                                  float* __restrict__ out) {
    const int b   = blockIdx.x;
    const int tid = threadIdx.x;
    const int i   = tid >> 2;
    const int q   = tid & 3;
    const int j0  = q * 16;

    __shared__ float nrm[64];
    __shared__ float lg[64];
    __shared__ float ebuf[2][64];
    __shared__ float red[64];

    float* gb = g_gram + (size_t)b * NN * NN;

    if (tid < 64) {
        nrm[tid] = sqrtf(gb[tid * NN + tid]);
        lg[tid]  = logits[b * NN + tid];
        ebuf[0][tid] = 0.0f;
    }
    __syncthreads();

    const float ni = nrm[i];
    float pp[16];
#pragma unroll
    for (int jj = 0; jj < 16; ++jj) {
        const int j = j0 + jj;
        const float dot  = gb[i * NN + j];
        const float sim  = dot / (ni * nrm[j] + 1e-6f);
        const float wsym = 0.5f * (W[i * NN + j] + W[j * NN + i]);
        pp[jj] = sim * wsym;
    }
#pragma unroll
    for (int jj = 0; jj < 16; jj += 4)
        *reinterpret_cast<float4*>(&gb[i * NN + j0 + jj]) = make_float4(0.f, 0.f, 0.f, 0.f);

    const float li = lg[i];
    int cur = 0;
    for (int it = 0; it < ITERS; ++it) {
        float acc = 0.0f;
        const float* e = ebuf[cur];
#pragma unroll
        for (int jj = 0; jj < 16; ++jj) {
            const float x = li + e[j0 + jj];
            float t, r;
            asm("ex2.approx.f32 %0, %1;" : "=f"(t) : "f"(x * -1.4426950408889634f));
            asm("rcp.approx.f32 %0, %1;" : "=f"(r) : "f"(1.0f + t));
            acc = fmaf((1.0f - t) * r, pp[jj], acc);
        }
        acc += __shfl_xor_sync(0xFFFFFFFF, acc, 1);
        acc += __shfl_xor_sync(0xFFFFFFFF, acc, 2);
        if (q == 0) ebuf[cur ^ 1][i] = acc;
        __syncthreads();
        cur ^= 1;
    }

    if (tid < 64) red[tid] = ebuf[cur][tid];
    __syncthreads();
    if (tid < 32) {
        float v = red[tid] + red[tid + 32];
        v += __shfl_xor_sync(0xFFFFFFFF, v, 16);
        v += __shfl_xor_sync(0xFFFFFFFF, v, 8);
        v += __shfl_xor_sync(0xFFFFFFFF, v, 4);
        v += __shfl_xor_sync(0xFFFFFFFF, v, 2);
        v += __shfl_xor_sync(0xFFFFFFFF, v, 1);
        if (tid == 0) red[0] = v;
    }
    __syncthreads();
    if (tid < 64) {
        const float meanE = red[0] * (1.0f / 64.0f);
        out[b * NN + tid] = lg[tid] + meanE;
    }
}

extern "C" void kernel_launch(void* const* d_in, const int* in_sizes, int n_in,
                              void* d_out, int out_size) {
    const float* a_inter = (const float*)d_in[0];  // [8,64,64,32,32]
    const float* logits  = (const float*)d_in[1];  // [8,64]
    const float* W       = (const float*)d_in[2];  // [1,64,64]
    float* out           = (float*)d_out;          // [8,64]

    // opt-in to >48KB dynamic smem (idempotent; no allocation; capture-safe)
    cudaFuncSetAttribute(gram_mma_kernel,
                         cudaFuncAttributeMaxDynamicSharedMemorySize, DSMEM_BYTES);

    dim3 grid(SPLITS, BATCH);
    gram_mma_kernel<<<grid, NTHREADS, DSMEM_BYTES>>>(a_inter);

    crf_kernel<<<BATCH, 256>>>(logits, W, out);
}